// round 12
// baseline (speedup 1.0000x reference)
#include <cuda_runtime.h>
#include <math.h>

// Problem constants
#define NN 4096
#define KK 8
#define DD 512
#define HH 512
#define G4 2048   // 4*H

// ---------------- static device scratch (no allocations allowed) ----------------
__device__ float g_WlhhT[HH * G4];     // [j][4e+gate] = Wl_hh[gate*512+e][j]
__device__ float g_WrhhT[HH * G4];
__device__ float g_WlihT[DD * G4];     // [k][4e+gate] = Wl_ih[gate*512+e][k]
__device__ float g_WrihT[DD * G4];
__device__ float g_WencT[2 * HH * DD]; // [j][e] = W_enc[e][j]
__device__ float g_biasL[G4];          // interleaved bih+bhh
__device__ float g_biasR[G4];
__device__ float g_AxL[NN * G4];       // x-term gate preactivations (incl. biases)
__device__ float g_AxR[NN * G4];
__device__ float g_AeL[NN * G4];       // enc-term gate preactivations (incl. biases)
__device__ float g_AeR[NN * G4];
__device__ int   g_ready[NN];
__device__ int   g_counter;

// ---------------- small helpers ----------------
__device__ __forceinline__ float sigf(float x) { return 1.0f / (1.0f + expf(-x)); }

__device__ __forceinline__ int ld_acquire(const int* p) {
    int v;
    asm volatile("ld.acquire.gpu.b32 %0, [%1];" : "=r"(v) : "l"(p) : "memory");
    return v;
}
__device__ __forceinline__ void st_release(int* p, int v) {
    asm volatile("st.release.gpu.b32 [%0], %1;" :: "l"(p), "r"(v) : "memory");
}
__device__ __forceinline__ void chain_bar(int chain) {
    asm volatile("bar.sync %0, %1;" :: "r"(chain + 1), "r"(512) : "memory");
}

// ---------------- reset ----------------
__global__ void reset_kernel() {
    int i = blockIdx.x * blockDim.x + threadIdx.x;
    if (i < NN) g_ready[i] = 0;
    if (i == 0) g_counter = 0;
}

// ---------------- preprocess: transpose + gate-interleave weights ----------------
__global__ void prep_kernel(const float* __restrict__ Wl_ih, const float* __restrict__ Wl_hh,
                            const float* __restrict__ Wr_ih, const float* __restrict__ Wr_hh,
                            const float* __restrict__ bl_ih, const float* __restrict__ bl_hh,
                            const float* __restrict__ br_ih, const float* __restrict__ br_hh,
                            const float* __restrict__ W_enc) {
    int idx = blockIdx.x * blockDim.x + threadIdx.x;
    int z = blockIdx.y;
    if (z < 4) {
        if (idx < 512 * 2048) {
            int j = idx >> 11, col = idx & 2047;
            int e = col >> 2, g = col & 3;
            const float* src = (z == 0) ? Wl_hh : (z == 1) ? Wr_hh : (z == 2) ? Wl_ih : Wr_ih;
            float* dst = (z == 0) ? g_WlhhT : (z == 1) ? g_WrhhT : (z == 2) ? g_WlihT : g_WrihT;
            dst[idx] = src[(g * 512 + e) * 512 + j];
        }
    } else {
        if (idx < 1024 * 512) {
            int j = idx >> 9, e = idx & 511;
            g_WencT[idx] = W_enc[e * 1024 + j];
        }
        if (idx < 2048) {
            int e = idx >> 2, g = idx & 3;
            int r = g * 512 + e;
            g_biasL[idx] = bl_ih[r] + bl_hh[r];
            g_biasR[idx] = br_ih[r] + br_hh[r];
        }
    }
}

// ---------------- batched GEMM: Ax = x0 @ WihT_int + bias  ([4096,512]x[512,2048]) ----------------
#define BM 128
#define BN 128
#define BK 8
__global__ __launch_bounds__(256) void gemm_ax(const float* __restrict__ x0) {
    int z = blockIdx.z;
    const float* B = z ? g_WrihT : g_WlihT;
    const float* bias = z ? g_biasR : g_biasL;
    float* C = z ? g_AxR : g_AxL;
    int n0 = blockIdx.x * BN;   // over 2048
    int m0 = blockIdx.y * BM;   // over 4096

    __shared__ float As[BK][BM + 4];
    __shared__ float Bs[BK][BN];

    float acc[8][8];
#pragma unroll
    for (int i = 0; i < 8; i++)
#pragma unroll
        for (int j = 0; j < 8; j++) acc[i][j] = 0.0f;

    int u = threadIdx.x;
    int tm = (u >> 4) * 8;
    int tn = (u & 15) * 8;

    for (int k0 = 0; k0 < 512; k0 += BK) {
        {
            int row = u >> 1, kk = (u & 1) * 4;
            float4 a4 = *(const float4*)&x0[(m0 + row) * 512 + k0 + kk];
            As[kk + 0][row] = a4.x; As[kk + 1][row] = a4.y;
            As[kk + 2][row] = a4.z; As[kk + 3][row] = a4.w;
        }
        {
            int kb = u >> 5, cc = (u & 31) * 4;
            *(float4*)&Bs[kb][cc] = *(const float4*)&B[(k0 + kb) * 2048 + n0 + cc];
        }
        __syncthreads();
#pragma unroll
        for (int k = 0; k < BK; k++) {
            float a[8], b[8];
            *(float4*)(a)     = *(float4*)&As[k][tm];
            *(float4*)(a + 4) = *(float4*)&As[k][tm + 4];
            *(float4*)(b)     = *(float4*)&Bs[k][tn];
            *(float4*)(b + 4) = *(float4*)&Bs[k][tn + 4];
#pragma unroll
            for (int i = 0; i < 8; i++)
#pragma unroll
                for (int j = 0; j < 8; j++) acc[i][j] += a[i] * b[j];
        }
        __syncthreads();
    }
#pragma unroll
    for (int i = 0; i < 8; i++) {
#pragma unroll
        for (int j = 0; j < 8; j += 4) {
            float4 o;
            o.x = acc[i][j + 0] + bias[n0 + tn + j + 0];
            o.y = acc[i][j + 1] + bias[n0 + tn + j + 1];
            o.z = acc[i][j + 2] + bias[n0 + tn + j + 2];
            o.w = acc[i][j + 3] + bias[n0 + tn + j + 3];
            *(float4*)&C[(m0 + tm + i) * 2048 + n0 + tn + j] = o;
        }
    }
}

// ---------------- persistent tree kernel ----------------
__global__ void __launch_bounds__(1024, 1) tree_kernel(
    const int* __restrict__ lch, const int* __restrict__ rch, int chstride,
    const float* __restrict__ b_enc, float* __restrict__ out) {

    __shared__ float sh_hL[512];
    __shared__ float sh_hR[512];
    __shared__ float sh_enc[512];
    __shared__ float sh_part[1024];
    __shared__ float sh_benc[512];
    __shared__ int   s_ch[16];
    __shared__ int   s_node;

    int tid = threadIdx.x;
    int chain = tid >> 9;        // 0 = left, 1 = right
    int t = tid & 511;

    if (tid < 512) sh_benc[tid] = b_enc[tid];

    const float4* Whq   = (const float4*)(chain ? g_WrhhT : g_WlhhT);
    const float4* Wiq   = (const float4*)(chain ? g_WrihT : g_WlihT);
    const float4* Axq   = (const float4*)(chain ? g_AxR : g_AxL);
    const float4* Aeq   = (const float4*)(chain ? g_AeR : g_AeL);
    float4*       AeOut = (float4*)(chain ? g_AeR : g_AeL);
    const float4* biasq = (const float4*)(chain ? g_biasR : g_biasL);
    float* sh_h = chain ? sh_hR : sh_hL;

    while (true) {
        __syncthreads();
        if (tid == 0) s_node = atomicAdd(&g_counter, 1);
        __syncthreads();
        int i = s_node;
        if (i >= NN) break;

        // stage children into shared (stride handles int32 or int64 input)
        if (tid < 8)        s_ch[tid] = lch[(i * 8 + tid) * chstride];
        else if (tid < 16)  s_ch[tid] = rch[(i * 8 + (tid - 8)) * chstride];
        __syncthreads();

        // wait for all children to be ready
        if (tid < 16) {
            int c = s_ch[tid];
            if (c >= 0) {
                while (ld_acquire(&g_ready[c]) == 0) { __nanosleep(64); }
            }
        }
        __syncthreads();

        // -------- chain LSTM (both chains run concurrently in half-blocks) --------
        // step 0: h=c=0 -> g = Ax (biases folded in)
        float cc;
        {
            float4 g4 = Axq[i * 512 + t];
            float ig = sigf(g4.x);
            float gg = tanhf(g4.z);
            cc = ig * gg;                       // f*0 + i*tanh(g)
            float oo = sigf(g4.w);
            sh_h[t] = oo * tanhf(cc);
        }
        chain_bar(chain);

        const int* mych = &s_ch[chain * 8];
        for (int k = 0; k < 8; k++) {
            int cj = mych[k];
            if (cj < 0) break;

            // acc = h @ Whh^T (gate-interleaved columns 4t..4t+3)
            float4 acc; acc.x = acc.y = acc.z = acc.w = 0.0f;
            const float4* hq = (const float4*)sh_h;
#pragma unroll 2
            for (int j4 = 0; j4 < 128; j4++) {
                float4 h4 = hq[j4];
                const float4* wp = Whq + (j4 * 4) * 512 + t;
                float4 w0 = wp[0];
                float4 w1 = wp[512];
                float4 w2 = wp[1024];
                float4 w3 = wp[1536];
                acc.x += w0.x * h4.x + w1.x * h4.y + w2.x * h4.z + w3.x * h4.w;
                acc.y += w0.y * h4.x + w1.y * h4.y + w2.y * h4.z + w3.y * h4.w;
                acc.z += w0.z * h4.x + w1.z * h4.y + w2.z * h4.z + w3.z * h4.w;
                acc.w += w0.w * h4.x + w1.w * h4.y + w2.w * h4.z + w3.w * h4.w;
            }
            float4 a4 = Aeq[cj * 512 + t];
            float ig = sigf(acc.x + a4.x);
            float ff = sigf(acc.y + a4.y);
            float gg = tanhf(acc.z + a4.z);
            float oo = sigf(acc.w + a4.w);
            cc = ff * cc + ig * gg;
            float hh = oo * tanhf(cc);
            chain_bar(chain);       // all reads of sh_h done
            sh_h[t] = hh;
            chain_bar(chain);       // writes visible to whole chain
        }
        __syncthreads();            // both chains done

        // -------- encoder: enc = tanh(Wenc @ [hl;hr] + b_enc) --------
        {
            float accp = 0.0f;
            const float* srch = chain ? sh_hR : sh_hL;
            const float* Wt = g_WencT + (chain * 512) * 512;
            for (int j = 0; j < 512; j++)
                accp += Wt[j * 512 + t] * srch[j];
            sh_part[tid] = accp;
        }
        __syncthreads();
        if (tid < 512) {
            float e = tanhf(sh_part[tid] + sh_part[512 + tid] + sh_benc[tid]);
            sh_enc[tid] = e;
            out[i * 512 + tid] = e;
        }
        __syncthreads();

        // -------- produce Ae for parents: Wih @ enc + biases --------
        {
            float4 acc = biasq[t];
            const float4* eq = (const float4*)sh_enc;
#pragma unroll 2
            for (int j4 = 0; j4 < 128; j4++) {
                float4 e4 = eq[j4];
                const float4* wp = Wiq + (j4 * 4) * 512 + t;
                float4 w0 = wp[0];
                float4 w1 = wp[512];
                float4 w2 = wp[1024];
                float4 w3 = wp[1536];
                acc.x += w0.x * e4.x + w1.x * e4.y + w2.x * e4.z + w3.x * e4.w;
                acc.y += w0.y * e4.x + w1.y * e4.y + w2.y * e4.z + w3.y * e4.w;
                acc.z += w0.z * e4.x + w1.z * e4.y + w2.z * e4.z + w3.z * e4.w;
                acc.w += w0.w * e4.x + w1.w * e4.y + w2.w * e4.z + w3.w * e4.w;
            }
            AeOut[i * 512 + t] = acc;
        }
        __threadfence();
        __syncthreads();
        if (tid == 0) st_release(&g_ready[i], 1);
    }
}

// ---------------- launch ----------------
extern "C" void kernel_launch(void* const* d_in, const int* in_sizes, int n_in,
                              void* d_out, int out_size) {
    const float* x0    = (const float*)d_in[0];
    const float* Wl_ih = (const float*)d_in[1];
    const float* Wl_hh = (const float*)d_in[2];
    const float* bl_ih = (const float*)d_in[3];
    const float* bl_hh = (const float*)d_in[4];
    const float* Wr_ih = (const float*)d_in[5];
    const float* Wr_hh = (const float*)d_in[6];
    const float* br_ih = (const float*)d_in[7];
    const float* br_hh = (const float*)d_in[8];
    const float* W_enc = (const float*)d_in[9];
    const float* b_enc = (const float*)d_in[10];
    const int*   lch   = (const int*)d_in[11];
    const int*   rch   = (const int*)d_in[12];
    float* out = (float*)d_out;

    // children may be serialized as int32 (stride 1) or int64 (stride 2, LE low word)
    int chstride = in_sizes[11] / (NN * KK);
    if (chstride < 1) chstride = 1;

    reset_kernel<<<16, 256>>>();

    dim3 pgrid((512 * 2048 + 255) / 256, 5);
    prep_kernel<<<pgrid, 256>>>(Wl_ih, Wl_hh, Wr_ih, Wr_hh,
                                bl_ih, bl_hh, br_ih, br_hh, W_enc);

    dim3 ggrid(2048 / BN, NN / BM, 2);
    gemm_ax<<<ggrid, 256>>>(x0);

    int sm = 148;
    cudaDeviceGetAttribute(&sm, cudaDevAttrMultiProcessorCount, 0);
    tree_kernel<<<sm, 1024>>>(lch, rch, chstride, b_enc, out);
}

// round 13
// speedup vs baseline: 1.2974x; 1.2974x over previous
#include <cuda_runtime.h>
#include <math.h>

#define NN 4096
#define KK 8
#define DD 512
#define HH 512
#define G4 2048
#define MAXLEV 4096
#define TM 32
#define TN 128
#define BKC 32

// ---------------- static device scratch ----------------
__device__ __align__(16) float g_WlhhT[HH * G4];
__device__ __align__(16) float g_WrhhT[HH * G4];
__device__ __align__(16) float g_WlihT[DD * G4];
__device__ __align__(16) float g_WrihT[DD * G4];
__device__ __align__(16) float g_WencT[2 * HH * DD];
__device__ __align__(16) float g_biasL[G4];
__device__ __align__(16) float g_biasR[G4];
__device__ __align__(16) float g_AxL[NN * G4];
__device__ __align__(16) float g_AxR[NN * G4];
__device__ __align__(16) float g_AeL[NN * G4];
__device__ __align__(16) float g_AeR[NN * G4];
__device__ __align__(16) float g_h[2][2][NN * HH];   // [parity][side]
__device__ __align__(16) float g_c[2][NN * HH];      // [side]

// scheduling state
__device__ int g_chL[NN * 8], g_chR[NN * 8];
__device__ int g_lcnt[NN], g_rcnt[NN];
__device__ int g_lvl[NN];
__device__ int g_lvlCount[MAXLEV];
__device__ int g_lvlStart[MAXLEV + 1];
__device__ int g_cnt2L[MAXLEV * 9], g_cnt2R[MAXLEV * 9];
__device__ int g_cntL[MAXLEV * 10], g_cntR[MAXLEV * 10];
__device__ int g_curL[MAXLEV * 9], g_curR[MAXLEV * 9];
__device__ int g_orderL[NN], g_orderR[NN];
__device__ int g_maxK[MAXLEV];
__device__ int g_numLevels;
__device__ int g_barArrive;
__device__ int g_barGen;

// ---------------- helpers ----------------
__device__ __forceinline__ float sigf(float x) { return 1.0f / (1.0f + expf(-x)); }

__device__ __forceinline__ int ld_acquire(const int* p) {
    int v;
    asm volatile("ld.acquire.gpu.b32 %0, [%1];" : "=r"(v) : "l"(p) : "memory");
    return v;
}
__device__ __forceinline__ void st_release(int* p, int v) {
    asm volatile("st.release.gpu.b32 [%0], %1;" :: "l"(p), "r"(v) : "memory");
}

__device__ __forceinline__ void grid_bar() {
    __syncthreads();
    if (threadIdx.x == 0) {
        __threadfence();
        int gen = ld_acquire(&g_barGen);
        int a = atomicAdd(&g_barArrive, 1);
        if (a == (int)gridDim.x - 1) {
            g_barArrive = 0;
            __threadfence();
            st_release(&g_barGen, gen + 1);
        } else {
            while (ld_acquire(&g_barGen) == gen) { __nanosleep(64); }
        }
    }
    __syncthreads();
}

// ---------------- reset ----------------
__global__ void reset_kernel() {
    int idx = blockIdx.x * blockDim.x + threadIdx.x;
    int st = gridDim.x * blockDim.x;
    for (int i = idx; i < NN; i += st) g_lvl[i] = -1;
    for (int i = idx; i < MAXLEV; i += st) { g_lvlCount[i] = 0; g_maxK[i] = 0; }
    for (int i = idx; i < MAXLEV * 9; i += st) { g_cnt2L[i] = 0; g_cnt2R[i] = 0; }
    if (idx == 0) { g_barArrive = 0; g_barGen = 0; }
}

// ---------------- weight prep (transpose + gate interleave) ----------------
__global__ void prep_kernel(const float* __restrict__ Wl_ih, const float* __restrict__ Wl_hh,
                            const float* __restrict__ Wr_ih, const float* __restrict__ Wr_hh,
                            const float* __restrict__ bl_ih, const float* __restrict__ bl_hh,
                            const float* __restrict__ br_ih, const float* __restrict__ br_hh,
                            const float* __restrict__ W_enc) {
    int idx = blockIdx.x * blockDim.x + threadIdx.x;
    int z = blockIdx.y;
    if (z < 4) {
        if (idx < 512 * 2048) {
            int j = idx >> 11, col = idx & 2047;
            int e = col >> 2, g = col & 3;
            const float* src = (z == 0) ? Wl_hh : (z == 1) ? Wr_hh : (z == 2) ? Wl_ih : Wr_ih;
            float* dst = (z == 0) ? g_WlhhT : (z == 1) ? g_WrhhT : (z == 2) ? g_WlihT : g_WrihT;
            dst[idx] = src[(g * 512 + e) * 512 + j];
        }
    } else {
        if (idx < 1024 * 512) {
            int j = idx >> 9, e = idx & 511;
            g_WencT[idx] = W_enc[e * 1024 + j];
        }
        if (idx < 2048) {
            int e = idx >> 2, g = idx & 3;
            int r = g * 512 + e;
            g_biasL[idx] = bl_ih[r] + bl_hh[r];
            g_biasR[idx] = br_ih[r] + br_hh[r];
        }
    }
}

// ---------------- Ax = x0 @ WihT + bias ----------------
#define BM 128
#define BN 128
#define BK 8
__global__ __launch_bounds__(256) void gemm_ax(const float* __restrict__ x0) {
    int z = blockIdx.z;
    const float* B = z ? g_WrihT : g_WlihT;
    const float* bias = z ? g_biasR : g_biasL;
    float* C = z ? g_AxR : g_AxL;
    int n0 = blockIdx.x * BN;
    int m0 = blockIdx.y * BM;

    __shared__ float As[BK][BM + 4];
    __shared__ float Bs[BK][BN];

    float acc[8][8];
#pragma unroll
    for (int i = 0; i < 8; i++)
#pragma unroll
        for (int j = 0; j < 8; j++) acc[i][j] = 0.0f;

    int u = threadIdx.x;
    int tm = (u >> 4) * 8;
    int tn = (u & 15) * 8;

    for (int k0 = 0; k0 < 512; k0 += BK) {
        {
            int row = u >> 1, kk = (u & 1) * 4;
            float4 a4 = *(const float4*)&x0[(m0 + row) * 512 + k0 + kk];
            As[kk + 0][row] = a4.x; As[kk + 1][row] = a4.y;
            As[kk + 2][row] = a4.z; As[kk + 3][row] = a4.w;
        }
        {
            int kb = u >> 5, cc = (u & 31) * 4;
            *(float4*)&Bs[kb][cc] = *(const float4*)&B[(k0 + kb) * 2048 + n0 + cc];
        }
        __syncthreads();
#pragma unroll
        for (int k = 0; k < BK; k++) {
            float a[8], b[8];
            *(float4*)(a)     = *(float4*)&As[k][tm];
            *(float4*)(a + 4) = *(float4*)&As[k][tm + 4];
            *(float4*)(b)     = *(float4*)&Bs[k][tn];
            *(float4*)(b + 4) = *(float4*)&Bs[k][tn + 4];
#pragma unroll
            for (int i = 0; i < 8; i++)
#pragma unroll
                for (int j = 0; j < 8; j++) acc[i][j] += a[i] * b[j];
        }
        __syncthreads();
    }
#pragma unroll
    for (int i = 0; i < 8; i++) {
#pragma unroll
        for (int j = 0; j < 8; j += 4) {
            float4 o;
            o.x = acc[i][j + 0] + bias[n0 + tn + j + 0];
            o.y = acc[i][j + 1] + bias[n0 + tn + j + 1];
            o.z = acc[i][j + 2] + bias[n0 + tn + j + 2];
            o.w = acc[i][j + 3] + bias[n0 + tn + j + 3];
            *(float4*)&C[(m0 + tm + i) * 2048 + n0 + tn + j] = o;
        }
    }
}

// ---------------- step-0 state for all nodes, both sides ----------------
__global__ void init_state_kernel() {
    int idx = blockIdx.x * blockDim.x + threadIdx.x;
    int total = 2 * NN * 512;
    if (idx >= total) return;
    int side = idx / (NN * 512);
    int r = idx - side * (NN * 512);
    float4 g4 = ((const float4*)(side ? g_AxR : g_AxL))[r];
    float ig = sigf(g4.x);
    float gg = tanhf(g4.z);
    float oo = sigf(g4.w);
    float c0 = ig * gg;
    g_c[side][r] = c0;
    g_h[1][side][r] = oo * tanhf(c0);
}

// ---------------- scheduler: levels + sorted orders (1 block) ----------------
__global__ void sched_kernel(const int* __restrict__ lch, const int* __restrict__ rch, int stride) {
    int tid = threadIdx.x;
    for (int idx = tid; idx < NN * 8; idx += 1024) {
        g_chL[idx] = lch[idx * stride];
        g_chR[idx] = rch[idx * stride];
    }
    __syncthreads();
    for (int i = tid; i < NN; i += 1024) {
        int cl = 0, cr = 0;
#pragma unroll
        for (int k = 0; k < 8; k++) {
            if (g_chL[i * 8 + k] >= 0) cl++;
            if (g_chR[i * 8 + k] >= 0) cr++;
        }
        g_lcnt[i] = cl; g_rcnt[i] = cr;
    }
    __syncthreads();

    volatile int* vl = g_lvl;
    __shared__ int sh_changed;
    for (int pass = 0; pass < NN; pass++) {
        if (tid == 0) sh_changed = 0;
        __syncthreads();
        for (int i = tid; i < NN; i += 1024) {
            if (vl[i] < 0) {
                int m = -1; bool ok = true;
#pragma unroll
                for (int k = 0; k < 8; k++) {
                    int c = g_chL[i * 8 + k];
                    if (c >= 0) { int lc = vl[c]; if (lc < 0) { ok = false; } else if (lc > m) m = lc; }
                    c = g_chR[i * 8 + k];
                    if (c >= 0) { int lc = vl[c]; if (lc < 0) { ok = false; } else if (lc > m) m = lc; }
                }
                if (ok) { vl[i] = m + 1; sh_changed = 1; }
            }
        }
        __syncthreads();
        if (!sh_changed) break;
    }

    __shared__ int sh_max;
    if (tid == 0) sh_max = 0;
    __syncthreads();
    for (int i = tid; i < NN; i += 1024) {
        int v = g_lvl[i];
        atomicMax(&sh_max, v);
        atomicAdd(&g_lvlCount[v], 1);
        atomicAdd(&g_cnt2L[v * 9 + g_lcnt[i]], 1);
        atomicAdd(&g_cnt2R[v * 9 + g_rcnt[i]], 1);
        int mk = g_lcnt[i] > g_rcnt[i] ? g_lcnt[i] : g_rcnt[i];
        atomicMax(&g_maxK[v], mk);
    }
    __syncthreads();
    int nl = sh_max + 1;
    if (tid == 0) {
        g_numLevels = nl;
        int s = 0;
        for (int v = 0; v < nl; v++) { g_lvlStart[v] = s; s += g_lvlCount[v]; }
        g_lvlStart[nl] = s;
    }
    __syncthreads();
    for (int v = tid; v < nl; v += 1024) {
        int ls = g_lvlStart[v];
        int s = 0;
        g_cntL[v * 10 + 9] = 0;
        for (int k = 8; k >= 0; k--) {
            g_curL[v * 9 + k] = ls + s;
            s += g_cnt2L[v * 9 + k];
            g_cntL[v * 10 + k] = s;
        }
        s = 0;
        g_cntR[v * 10 + 9] = 0;
        for (int k = 8; k >= 0; k--) {
            g_curR[v * 9 + k] = ls + s;
            s += g_cnt2R[v * 9 + k];
            g_cntR[v * 10 + k] = s;
        }
    }
    __syncthreads();
    for (int i = tid; i < NN; i += 1024) {
        int v = g_lvl[i];
        int p = atomicAdd(&g_curL[v * 9 + g_lcnt[i]], 1);
        g_orderL[p] = i;
        p = atomicAdd(&g_curR[v * 9 + g_rcnt[i]], 1);
        g_orderR[p] = i;
    }
}

// ---------------- persistent level-batched compute ----------------
__global__ __launch_bounds__(256, 4) void level_kernel(const float* __restrict__ b_enc,
                                                       float* __restrict__ out) {
    __shared__ float Ws[BKC][TN];          // 16KB
    __shared__ float Hs[BKC][TM + 4];      // 4.6KB
    __shared__ const float* rowp[TM];
    __shared__ const float* rowp2[TM];
    __shared__ int s_ids[TM];
    __shared__ int s_child[TM];

    int tid = threadIdx.x;
    int tx = tid & 31, ty = tid >> 5;
    int nb = gridDim.x;

    int numLev = g_numLevels;
    for (int v = 0; v < numLev; v++) {
        int base = g_lvlStart[v];
        int sz = g_lvlStart[v + 1] - base;
        int mk = g_maxK[v];

        // ---- chain steps ----
        for (int k = 1; k <= mk; k++) {
            int ML = g_cntL[v * 10 + k];
            int MR = g_cntR[v * 10 + k];
            int tL = ((ML + 31) >> 5) << 4;
            int tR = ((MR + 31) >> 5) << 4;
            const float* hin0 = g_h[k & 1][0];
            const float* hin1 = g_h[k & 1][1];
            float* hout0 = g_h[(k + 1) & 1][0];
            float* hout1 = g_h[(k + 1) & 1][1];
            for (int t = blockIdx.x; t < tL + tR; t += nb) {
                int side = (t >= tL);
                int tt = side ? (t - tL) : t;
                int mblk = tt >> 4, nblk = tt & 15;
                int cnt = side ? MR : ML;
                const int* order = side ? g_orderR : g_orderL;
                const int* ch = side ? g_chR : g_chL;
                const float* W = side ? g_WrhhT : g_WlhhT;
                const float* hin = side ? hin1 : hin0;
                float* hout = side ? hout1 : hout0;
                float* cst = g_c[side];
                const float4* Aeq = (const float4*)(side ? g_AeR : g_AeL);

                __syncthreads();
                if (tid < TM) {
                    int mg = mblk * TM + tid;
                    int id = (mg < cnt) ? order[base + mg] : -1;
                    s_ids[tid] = id;
                    int cj = (id >= 0) ? ch[id * 8 + (k - 1)] : 0;
                    s_child[tid] = (cj < 0) ? 0 : cj;
                    rowp[tid] = hin + ((id >= 0) ? id : 0) * 512;
                }
                __syncthreads();

                float acc[4][4];
#pragma unroll
                for (int a = 0; a < 4; a++)
#pragma unroll
                    for (int b = 0; b < 4; b++) acc[a][b] = 0.0f;

                int n0 = nblk * TN;
                int jr0 = tid >> 5;
                int c4 = (tid & 31) * 4;
                int hm = tid >> 3, hq = (tid & 7) * 4;
                for (int j0 = 0; j0 < 512; j0 += BKC) {
#pragma unroll
                    for (int p = 0; p < 4; p++) {
                        int jr = jr0 + p * 8;
                        *(float4*)&Ws[jr][c4] = *(const float4*)&W[(j0 + jr) * 2048 + n0 + c4];
                    }
                    {
                        float4 hv = *(const float4*)(rowp[hm] + j0 + hq);
                        Hs[hq + 0][hm] = hv.x; Hs[hq + 1][hm] = hv.y;
                        Hs[hq + 2][hm] = hv.z; Hs[hq + 3][hm] = hv.w;
                    }
                    __syncthreads();
#pragma unroll
                    for (int jj = 0; jj < BKC; jj++) {
                        float4 b4 = *(float4*)&Ws[jj][tx * 4];
                        float4 a4 = *(float4*)&Hs[jj][ty * 4];
                        acc[0][0] += a4.x * b4.x; acc[0][1] += a4.x * b4.y; acc[0][2] += a4.x * b4.z; acc[0][3] += a4.x * b4.w;
                        acc[1][0] += a4.y * b4.x; acc[1][1] += a4.y * b4.y; acc[1][2] += a4.y * b4.z; acc[1][3] += a4.y * b4.w;
                        acc[2][0] += a4.z * b4.x; acc[2][1] += a4.z * b4.y; acc[2][2] += a4.z * b4.z; acc[2][3] += a4.z * b4.w;
                        acc[3][0] += a4.w * b4.x; acc[3][1] += a4.w * b4.y; acc[3][2] += a4.w * b4.z; acc[3][3] += a4.w * b4.w;
                    }
                    __syncthreads();
                }
                int e = (n0 >> 2) + tx;
#pragma unroll
                for (int mi = 0; mi < 4; mi++) {
                    int m = ty * 4 + mi;
                    int id = s_ids[m];
                    if (id < 0) continue;
                    float4 a4 = Aeq[s_child[m] * 512 + e];
                    float ig = sigf(acc[mi][0] + a4.x);
                    float ff = sigf(acc[mi][1] + a4.y);
                    float gg = tanhf(acc[mi][2] + a4.z);
                    float oo = sigf(acc[mi][3] + a4.w);
                    float cold = cst[id * 512 + e];
                    float cn = ff * cold + ig * gg;
                    cst[id * 512 + e] = cn;
                    hout[id * 512 + e] = oo * tanhf(cn);
                }
            }
            grid_bar();
        }

        // ---- encoder: enc = tanh([hl;hr] @ WencT + b_enc) -> out ----
        {
            int tE = ((sz + 31) >> 5) * 4;
            for (int t = blockIdx.x; t < tE; t += nb) {
                int mblk = t >> 2, nblk = t & 3;
                __syncthreads();
                if (tid < TM) {
                    int mg = mblk * TM + tid;
                    int id = (mg < sz) ? g_orderL[base + mg] : -1;
                    s_ids[tid] = id;
                    int iu = (id >= 0) ? id : 0;
                    int pL = (g_lcnt[iu] + 1) & 1;
                    int pR = (g_rcnt[iu] + 1) & 1;
                    rowp[tid]  = &g_h[pL][0][iu * 512];
                    rowp2[tid] = &g_h[pR][1][iu * 512];
                }
                __syncthreads();

                float acc[4][4];
#pragma unroll
                for (int a = 0; a < 4; a++)
#pragma unroll
                    for (int b = 0; b < 4; b++) acc[a][b] = 0.0f;

                int n0 = nblk * TN;
                int jr0 = tid >> 5;
                int c4 = (tid & 31) * 4;
                int hm = tid >> 3, hq = (tid & 7) * 4;
                for (int j0 = 0; j0 < 1024; j0 += BKC) {
#pragma unroll
                    for (int p = 0; p < 4; p++) {
                        int jr = jr0 + p * 8;
                        *(float4*)&Ws[jr][c4] = *(const float4*)&g_WencT[(j0 + jr) * 512 + n0 + c4];
                    }
                    {
                        const float* rp = (j0 >= 512) ? rowp2[hm] : rowp[hm];
                        float4 hv = *(const float4*)(rp + (j0 & 511) + hq);
                        Hs[hq + 0][hm] = hv.x; Hs[hq + 1][hm] = hv.y;
                        Hs[hq + 2][hm] = hv.z; Hs[hq + 3][hm] = hv.w;
                    }
                    __syncthreads();
#pragma unroll
                    for (int jj = 0; jj < BKC; jj++) {
                        float4 b4 = *(float4*)&Ws[jj][tx * 4];
                        float4 a4 = *(float4*)&Hs[jj][ty * 4];
                        acc[0][0] += a4.x * b4.x; acc[0][1] += a4.x * b4.y; acc[0][2] += a4.x * b4.z; acc[0][3] += a4.x * b4.w;
                        acc[1][0] += a4.y * b4.x; acc[1][1] += a4.y * b4.y; acc[1][2] += a4.y * b4.z; acc[1][3] += a4.y * b4.w;
                        acc[2][0] += a4.z * b4.x; acc[2][1] += a4.z * b4.y; acc[2][2] += a4.z * b4.z; acc[2][3] += a4.z * b4.w;
                        acc[3][0] += a4.w * b4.x; acc[3][1] += a4.w * b4.y; acc[3][2] += a4.w * b4.z; acc[3][3] += a4.w * b4.w;
                    }
                    __syncthreads();
                }
                int e0 = n0 + tx * 4;
                float4 bv = *(const float4*)&b_enc[e0];
#pragma unroll
                for (int mi = 0; mi < 4; mi++) {
                    int m = ty * 4 + mi;
                    int id = s_ids[m];
                    if (id < 0) continue;
                    float4 o;
                    o.x = tanhf(acc[mi][0] + bv.x);
                    o.y = tanhf(acc[mi][1] + bv.y);
                    o.z = tanhf(acc[mi][2] + bv.z);
                    o.w = tanhf(acc[mi][3] + bv.w);
                    *(float4*)&out[id * 512 + e0] = o;
                }
            }
            grid_bar();
        }

        // ---- Ae = Wih @ enc + biases (both sides) ----
        {
            int tA = ((sz + 31) >> 5) << 4;
            for (int t = blockIdx.x; t < 2 * tA; t += nb) {
                int side = (t >= tA);
                int tt = side ? (t - tA) : t;
                int mblk = tt >> 4, nblk = tt & 15;
                const float* W = side ? g_WrihT : g_WlihT;
                const float4* biasq = (const float4*)(side ? g_biasR : g_biasL);
                float4* AeO = (float4*)(side ? g_AeR : g_AeL);

                __syncthreads();
                if (tid < TM) {
                    int mg = mblk * TM + tid;
                    int id = (mg < sz) ? g_orderL[base + mg] : -1;
                    s_ids[tid] = id;
                    rowp[tid] = out + ((id >= 0) ? id : 0) * 512;
                }
                __syncthreads();

                float acc[4][4];
#pragma unroll
                for (int a = 0; a < 4; a++)
#pragma unroll
                    for (int b = 0; b < 4; b++) acc[a][b] = 0.0f;

                int n0 = nblk * TN;
                int jr0 = tid >> 5;
                int c4 = (tid & 31) * 4;
                int hm = tid >> 3, hq = (tid & 7) * 4;
                for (int j0 = 0; j0 < 512; j0 += BKC) {
#pragma unroll
                    for (int p = 0; p < 4; p++) {
                        int jr = jr0 + p * 8;
                        *(float4*)&Ws[jr][c4] = *(const float4*)&W[(j0 + jr) * 2048 + n0 + c4];
                    }
                    {
                        float4 hv = *(const float4*)(rowp[hm] + j0 + hq);
                        Hs[hq + 0][hm] = hv.x; Hs[hq + 1][hm] = hv.y;
                        Hs[hq + 2][hm] = hv.z; Hs[hq + 3][hm] = hv.w;
                    }
                    __syncthreads();
#pragma unroll
                    for (int jj = 0; jj < BKC; jj++) {
                        float4 b4 = *(float4*)&Ws[jj][tx * 4];
                        float4 a4 = *(float4*)&Hs[jj][ty * 4];
                        acc[0][0] += a4.x * b4.x; acc[0][1] += a4.x * b4.y; acc[0][2] += a4.x * b4.z; acc[0][3] += a4.x * b4.w;
                        acc[1][0] += a4.y * b4.x; acc[1][1] += a4.y * b4.y; acc[1][2] += a4.y * b4.z; acc[1][3] += a4.y * b4.w;
                        acc[2][0] += a4.z * b4.x; acc[2][1] += a4.z * b4.y; acc[2][2] += a4.z * b4.z; acc[2][3] += a4.z * b4.w;
                        acc[3][0] += a4.w * b4.x; acc[3][1] += a4.w * b4.y; acc[3][2] += a4.w * b4.z; acc[3][3] += a4.w * b4.w;
                    }
                    __syncthreads();
                }
                int e = (n0 >> 2) + tx;
                float4 b4 = biasq[e];
#pragma unroll
                for (int mi = 0; mi < 4; mi++) {
                    int m = ty * 4 + mi;
                    int id = s_ids[m];
                    if (id < 0) continue;
                    float4 o;
                    o.x = acc[mi][0] + b4.x;
                    o.y = acc[mi][1] + b4.y;
                    o.z = acc[mi][2] + b4.z;
                    o.w = acc[mi][3] + b4.w;
                    AeO[id * 512 + e] = o;
                }
            }
            grid_bar();
        }
    }
}

// ---------------- launch ----------------
extern "C" void kernel_launch(void* const* d_in, const int* in_sizes, int n_in,
                              void* d_out, int out_size) {
    const float* x0    = (const float*)d_in[0];
    const float* Wl_ih = (const float*)d_in[1];
    const float* Wl_hh = (const float*)d_in[2];
    const float* bl_ih = (const float*)d_in[3];
    const float* bl_hh = (const float*)d_in[4];
    const float* Wr_ih = (const float*)d_in[5];
    const float* Wr_hh = (const float*)d_in[6];
    const float* br_ih = (const float*)d_in[7];
    const float* br_hh = (const float*)d_in[8];
    const float* W_enc = (const float*)d_in[9];
    const float* b_enc = (const float*)d_in[10];
    const int*   lch   = (const int*)d_in[11];
    const int*   rch   = (const int*)d_in[12];
    float* out = (float*)d_out;

    int chstride = in_sizes[11] / (NN * KK);
    if (chstride < 1) chstride = 1;

    reset_kernel<<<256, 256>>>();

    dim3 pgrid((512 * 2048 + 255) / 256, 5);
    prep_kernel<<<pgrid, 256>>>(Wl_ih, Wl_hh, Wr_ih, Wr_hh,
                                bl_ih, bl_hh, br_ih, br_hh, W_enc);

    dim3 ggrid(2048 / BN, NN / BM, 2);
    gemm_ax<<<ggrid, 256>>>(x0);

    init_state_kernel<<<(2 * NN * 512 + 255) / 256, 256>>>();

    sched_kernel<<<1, 1024>>>(lch, rch, chstride);

    int sm = 148;
    cudaDeviceGetAttribute(&sm, cudaDevAttrMultiProcessorCount, 0);
    int occ = 0;
    cudaOccupancyMaxActiveBlocksPerMultiprocessor(&occ, level_kernel, 256, 0);
    if (occ < 1) occ = 1;
    if (occ > 4) occ = 4;
    int nb = sm * occ;
    level_kernel<<<nb, 256>>>(b_enc, out);
}